// round 13
// baseline (speedup 1.0000x reference)
#include <cuda_runtime.h>
#include <cuda_fp16.h>
#include <cstdint>

#define N_NODES 50000
#define D_FEAT  128
#define N_EDGES 800000
#define CAP     64          // per-row bucket capacity (max observed degree ~40)
#define OVF_CAP 4096

// Scratch (device globals; no allocation allowed)
__device__ __half             g_xh[(size_t)N_NODES * D_FEAT];     // 12.8 MB: fp16 tangent
__device__ unsigned long long g_bucket[(size_t)N_NODES * CAP];    // (col<<32)|val_bits
__device__ int                g_cnt[N_NODES];
__device__ int                g_ovf_cnt;
__device__ uint4              g_ovf[OVF_CAP];                     // {row, col, val_bits, _}

// ---------------------------------------------------------------------------
// Kernel Z: zero counters (runs on the side stream, immediately before scatter)
// ---------------------------------------------------------------------------
__global__ __launch_bounds__(256) void zero_kernel() {
    int t = blockIdx.x * blockDim.x + threadIdx.x;
    if (t < N_NODES) g_cnt[t] = 0;
    if (t == 0) g_ovf_cnt = 0;
}

// ---------------------------------------------------------------------------
// Kernel A: logmap0 factor + fp16 tangent convert. EXACT R12 math; counter
// zeroing removed (now in zero_kernel on the scatter stream).
// ---------------------------------------------------------------------------
__global__ __launch_bounds__(256) void factor_kernel(const float* __restrict__ x) {
    const int warp_id = (blockIdx.x * blockDim.x + threadIdx.x) >> 5;
    const int lane    = threadIdx.x & 31;
    const int l       = lane & 7;
    const int row     = warp_id * 4 + (lane >> 3);
    if (row >= N_NODES) return;

    const float4* xr = reinterpret_cast<const float4*>(x) + (size_t)row * 32;
    float4 v[4];
    #pragma unroll
    for (int k = 0; k < 4; k++) v[k] = xr[l + 8 * k];

    float ss = 0.f;
    #pragma unroll
    for (int k = 0; k < 4; k++)
        ss += v[k].x * v[k].x + v[k].y * v[k].y + v[k].z * v[k].z + v[k].w * v[k].w;
    ss += __shfl_xor_sync(0xFFFFFFFFu, ss, 1);
    ss += __shfl_xor_sync(0xFFFFFFFFu, ss, 2);
    ss += __shfl_xor_sync(0xFFFFFFFFu, ss, 4);

    // factor = artanh(min(norm, 1-eps)) / max(norm, 1e-15)
    float factor;
    if (ss < 0.0025f) {                      // norm < 0.05: series, err < 1e-12 rel
        factor = 1.0f + ss * (0.33333333f + ss * (0.2f + ss * 0.14285714f));
    } else {                                 // exact fallback (never taken here)
        float norm = fmaxf(sqrtf(ss), 1e-15f);
        float u = fminf(norm, 0.99999988f);
        factor = atanhf(u) / norm;
    }

    uint2* xh = reinterpret_cast<uint2*>(g_xh + (size_t)row * D_FEAT);
    #pragma unroll
    for (int k = 0; k < 4; k++) {
        __half2 lo = __floats2half2_rn(v[k].x * factor, v[k].y * factor);
        __half2 hi = __floats2half2_rn(v[k].z * factor, v[k].w * factor);
        uint2 packed;
        packed.x = *reinterpret_cast<unsigned*>(&lo);
        packed.y = *reinterpret_cast<unsigned*>(&hi);
        xh[l + 8 * k] = packed;
    }
}

// ---------------------------------------------------------------------------
// Kernel B: scatter — EXACT R11/R12 (4 edges/thread, vectorized edge loads).
// ---------------------------------------------------------------------------
__global__ __launch_bounds__(256) void scatter_kernel(
    const int* __restrict__ adj_rows,
    const int* __restrict__ adj_cols,
    const float* __restrict__ adj_vals)
{
    int t = blockIdx.x * blockDim.x + threadIdx.x;
    int e0 = t * 4;
    if (e0 >= N_EDGES) return;

    int4   r4 = reinterpret_cast<const int4*>(adj_rows)[t];
    int4   c4 = reinterpret_cast<const int4*>(adj_cols)[t];
    float4 v4 = reinterpret_cast<const float4*>(adj_vals)[t];

    int   r[4] = {r4.x, r4.y, r4.z, r4.w};
    int   c[4] = {c4.x, c4.y, c4.z, c4.w};
    float v[4] = {v4.x, v4.y, v4.z, v4.w};

    #pragma unroll
    for (int k = 0; k < 4; k++) {
        int pos = atomicAdd(&g_cnt[r[k]], 1);
        if (pos < CAP) {
            g_bucket[(size_t)r[k] * CAP + pos] =
                ((unsigned long long)(unsigned)c[k] << 32) | (unsigned)__float_as_uint(v[k]);
        } else {
            int o = atomicAdd(&g_ovf_cnt, 1);
            if (o < OVF_CAP)
                g_ovf[o] = make_uint4((unsigned)r[k], (unsigned)c[k], __float_as_uint(v[k]), 0u);
        }
    }
}

// ---------------------------------------------------------------------------
// Kernel C: aggregate — EXACT R12 (frozen loop body, 64-thread blocks).
// ---------------------------------------------------------------------------
__device__ __forceinline__ void acc_edge4(float* acc, unsigned long long p, int hl) {
    const uint4* row = reinterpret_cast<const uint4*>(g_xh + (size_t)(p >> 32) * D_FEAT);
    uint4 q = row[hl];
    float s = __uint_as_float((unsigned)p);
    float2 f0 = __half22float2(*reinterpret_cast<__half2*>(&q.x));
    float2 f1 = __half22float2(*reinterpret_cast<__half2*>(&q.y));
    float2 f2 = __half22float2(*reinterpret_cast<__half2*>(&q.z));
    float2 f3 = __half22float2(*reinterpret_cast<__half2*>(&q.w));
    acc[0] += s * f0.x; acc[1] += s * f0.y;
    acc[2] += s * f1.x; acc[3] += s * f1.y;
    acc[4] += s * f2.x; acc[5] += s * f2.y;
    acc[6] += s * f3.x; acc[7] += s * f3.y;
}

__global__ __launch_bounds__(64) void aggregate_kernel(float* __restrict__ out) {
    int gw   = (blockIdx.x * blockDim.x + threadIdx.x) >> 5;
    int lane = threadIdx.x & 31;
    if (gw >= N_NODES) return;

    const int half = lane >> 4;
    const int hl   = lane & 15;

    int raw_n = g_cnt[gw];
    int n = (raw_n < CAP) ? raw_n : CAP;
    const unsigned long long* bk = g_bucket + (size_t)gw * CAP;

    float acc[8] = {0.f, 0.f, 0.f, 0.f, 0.f, 0.f, 0.f, 0.f};

    int e = 0;
    for (; e + 4 <= n; e += 4) {
        unsigned long long p0 = bk[e + half];
        unsigned long long p1 = bk[e + 2 + half];
        acc_edge4(acc, p0, hl);
        acc_edge4(acc, p1, hl);
    }
    if (e + 2 <= n) {
        acc_edge4(acc, bk[e + half], hl);
        e += 2;
    }
    if (e < n && half == 0) {
        acc_edge4(acc, bk[e], hl);
    }

    if (raw_n > CAP && half == 0) {
        int ovf_n = g_ovf_cnt;
        ovf_n = (ovf_n < OVF_CAP) ? ovf_n : OVF_CAP;
        for (int i = 0; i < ovf_n; i++) {
            uint4 qo = g_ovf[i];
            if ((int)qo.x == gw) {
                unsigned long long p =
                    ((unsigned long long)qo.y << 32) | (unsigned long long)qo.z;
                acc_edge4(acc, p, hl);
            }
        }
    }

    #pragma unroll
    for (int i = 0; i < 8; i++)
        acc[i] += __shfl_xor_sync(0xFFFFFFFFu, acc[i], 16);

    if (half == 0) {
        float4* o4 = reinterpret_cast<float4*>(out) + (size_t)gw * 32 + hl * 2;
        o4[0] = make_float4(acc[0], acc[1], acc[2], acc[3]);
        o4[1] = make_float4(acc[4], acc[5], acc[6], acc[7]);
    }
}

// ---------------------------------------------------------------------------
// Launch: fork-join overlap (graph-capturable pattern):
//   main stream:  |--- factor ---------------|  wait(join)  aggregate
//   side stream:  wait(fork)  zero -> scatter  record(join)
// Stream/event lifecycle is host-side only; the captured graph holds just the
// kernel nodes + dependencies (no per-replay host cost).
// ---------------------------------------------------------------------------
extern "C" void kernel_launch(void* const* d_in, const int* in_sizes, int n_in,
                              void* d_out, int out_size) {
    const float* x        = (const float*)d_in[0];
    const int*   adj_rows = (const int*)  d_in[1];
    const int*   adj_cols = (const int*)  d_in[2];
    const float* adj_vals = (const float*)d_in[3];
    float*       out      = (float*)      d_out;

    cudaStream_t sB;
    cudaStreamCreateWithFlags(&sB, cudaStreamNonBlocking);
    cudaEvent_t evFork, evJoin;
    cudaEventCreateWithFlags(&evFork, cudaEventDisableTiming);
    cudaEventCreateWithFlags(&evJoin, cudaEventDisableTiming);

    // fork side stream off the (possibly capturing) main stream
    cudaEventRecord(evFork, 0);
    cudaStreamWaitEvent(sB, evFork, 0);

    // side branch: zero counters, then scatter (ordered within sB)
    zero_kernel<<<(N_NODES + 255) / 256, 256, 0, sB>>>();
    {
        int threads_total = N_EDGES / 4;
        scatter_kernel<<<(threads_total + 255) / 256, 256, 0, sB>>>(adj_rows, adj_cols, adj_vals);
    }
    cudaEventRecord(evJoin, sB);

    // main branch: factor runs concurrently with the side branch
    {
        int blocks = (N_NODES + 31) / 32;
        factor_kernel<<<blocks, 256>>>(x);
    }

    // join: aggregate needs factor (main-stream order) AND scatter (event)
    cudaStreamWaitEvent(0, evJoin, 0);
    {
        int blocks = N_NODES / 2;      // 2 nodes per 64-thread block
        aggregate_kernel<<<blocks, 64>>>(out);
    }

    cudaEventDestroy(evFork);
    cudaEventDestroy(evJoin);
    cudaStreamDestroy(sB);
}

// round 14
// speedup vs baseline: 1.0508x; 1.0508x over previous
#include <cuda_runtime.h>
#include <cuda_fp16.h>
#include <cstdint>

#define N_NODES 50000
#define D_FEAT  128
#define N_EDGES 800000
#define CAP     64          // per-row bucket capacity (max observed degree ~40)
#define OVF_CAP 4096

// Scratch (device globals; no allocation allowed)
__device__ __half             g_xh[(size_t)N_NODES * D_FEAT];     // 12.8 MB: fp16 tangent
__device__ unsigned long long g_bucket[(size_t)N_NODES * CAP];    // (col<<32)|val_bits
__device__ int                g_cnt[N_NODES];
__device__ int                g_ovf_cnt;
__device__ uint4              g_ovf[OVF_CAP];                     // {row, col, val_bits, _}

// ---------------------------------------------------------------------------
// Kernel A: logmap0 factor + fp16 tangent convert + zero counters. EXACT R12.
// ---------------------------------------------------------------------------
__global__ __launch_bounds__(256) void factor_kernel(const float* __restrict__ x) {
    const int warp_id = (blockIdx.x * blockDim.x + threadIdx.x) >> 5;
    const int lane    = threadIdx.x & 31;
    const int l       = lane & 7;
    const int row     = warp_id * 4 + (lane >> 3);

    int t = blockIdx.x * blockDim.x + threadIdx.x;
    if (t < N_NODES) g_cnt[t] = 0;
    if (t == 0) g_ovf_cnt = 0;

    if (row >= N_NODES) return;

    const float4* xr = reinterpret_cast<const float4*>(x) + (size_t)row * 32;
    float4 v[4];
    #pragma unroll
    for (int k = 0; k < 4; k++) v[k] = xr[l + 8 * k];

    float ss = 0.f;
    #pragma unroll
    for (int k = 0; k < 4; k++)
        ss += v[k].x * v[k].x + v[k].y * v[k].y + v[k].z * v[k].z + v[k].w * v[k].w;
    ss += __shfl_xor_sync(0xFFFFFFFFu, ss, 1);
    ss += __shfl_xor_sync(0xFFFFFFFFu, ss, 2);
    ss += __shfl_xor_sync(0xFFFFFFFFu, ss, 4);

    // factor = artanh(min(norm, 1-eps)) / max(norm, 1e-15)
    float factor;
    if (ss < 0.0025f) {                      // norm < 0.05: series, err < 1e-12 rel
        factor = 1.0f + ss * (0.33333333f + ss * (0.2f + ss * 0.14285714f));
    } else {                                 // exact fallback (never taken here)
        float norm = fmaxf(sqrtf(ss), 1e-15f);
        float u = fminf(norm, 0.99999988f);
        factor = atanhf(u) / norm;
    }

    uint2* xh = reinterpret_cast<uint2*>(g_xh + (size_t)row * D_FEAT);
    #pragma unroll
    for (int k = 0; k < 4; k++) {
        __half2 lo = __floats2half2_rn(v[k].x * factor, v[k].y * factor);
        __half2 hi = __floats2half2_rn(v[k].z * factor, v[k].w * factor);
        uint2 packed;
        packed.x = *reinterpret_cast<unsigned*>(&lo);
        packed.y = *reinterpret_cast<unsigned*>(&hi);
        xh[l + 8 * k] = packed;
    }
}

// ---------------------------------------------------------------------------
// Kernel B: scatter — EXACT R12 (4 edges/thread, vectorized edge loads).
// ---------------------------------------------------------------------------
__global__ __launch_bounds__(256) void scatter_kernel(
    const int* __restrict__ adj_rows,
    const int* __restrict__ adj_cols,
    const float* __restrict__ adj_vals)
{
    int t = blockIdx.x * blockDim.x + threadIdx.x;
    int e0 = t * 4;
    if (e0 >= N_EDGES) return;

    int4   r4 = reinterpret_cast<const int4*>(adj_rows)[t];
    int4   c4 = reinterpret_cast<const int4*>(adj_cols)[t];
    float4 v4 = reinterpret_cast<const float4*>(adj_vals)[t];

    int   r[4] = {r4.x, r4.y, r4.z, r4.w};
    int   c[4] = {c4.x, c4.y, c4.z, c4.w};
    float v[4] = {v4.x, v4.y, v4.z, v4.w};

    #pragma unroll
    for (int k = 0; k < 4; k++) {
        int pos = atomicAdd(&g_cnt[r[k]], 1);
        if (pos < CAP) {
            g_bucket[(size_t)r[k] * CAP + pos] =
                ((unsigned long long)(unsigned)c[k] << 32) | (unsigned)__float_as_uint(v[k]);
        } else {
            int o = atomicAdd(&g_ovf_cnt, 1);
            if (o < OVF_CAP)
                g_ovf[o] = make_uint4((unsigned)r[k], (unsigned)c[k], __float_as_uint(v[k]), 0u);
        }
    }
}

// ---------------------------------------------------------------------------
// Kernel C: aggregate — ONE CHANGE vs R12: mixed-precision fma.rn.f32.f16
// replaces the 8 half->float converts + 8 FFMA per edge with 1 cvt + 8 HFMA
// (fp32 accumulate). fp16 products are exact in fp32; only the edge scale's
// fp16 quantization adds error (~2^-11 rel).
// ---------------------------------------------------------------------------
__device__ __forceinline__ void acc_edge4(float* acc, unsigned long long p, int hl) {
    const uint4* row = reinterpret_cast<const uint4*>(g_xh + (size_t)(p >> 32) * D_FEAT);
    uint4 q = row[hl];

    // edge scale -> fp16 (once per edge)
    unsigned short sh;
    asm("cvt.rn.f16.f32 %0, %1;" : "=h"(sh) : "f"(__uint_as_float((unsigned)p)));

    #pragma unroll
    for (int j = 0; j < 4; j++) {
        unsigned w = (&q.x)[j];
        unsigned short lo = (unsigned short)(w & 0xFFFFu);
        unsigned short hi = (unsigned short)(w >> 16);
        asm("fma.rn.f32.f16 %0, %1, %2, %0;" : "+f"(acc[2*j])     : "h"(lo), "h"(sh));
        asm("fma.rn.f32.f16 %0, %1, %2, %0;" : "+f"(acc[2*j + 1]) : "h"(hi), "h"(sh));
    }
}

__global__ __launch_bounds__(64) void aggregate_kernel(float* __restrict__ out) {
    int gw   = (blockIdx.x * blockDim.x + threadIdx.x) >> 5;
    int lane = threadIdx.x & 31;
    if (gw >= N_NODES) return;

    const int half = lane >> 4;
    const int hl   = lane & 15;

    int raw_n = g_cnt[gw];
    int n = (raw_n < CAP) ? raw_n : CAP;
    const unsigned long long* bk = g_bucket + (size_t)gw * CAP;

    float acc[8] = {0.f, 0.f, 0.f, 0.f, 0.f, 0.f, 0.f, 0.f};

    int e = 0;
    for (; e + 4 <= n; e += 4) {
        unsigned long long p0 = bk[e + half];
        unsigned long long p1 = bk[e + 2 + half];
        acc_edge4(acc, p0, hl);
        acc_edge4(acc, p1, hl);
    }
    if (e + 2 <= n) {
        acc_edge4(acc, bk[e + half], hl);
        e += 2;
    }
    if (e < n && half == 0) {
        acc_edge4(acc, bk[e], hl);
    }

    if (raw_n > CAP && half == 0) {
        int ovf_n = g_ovf_cnt;
        ovf_n = (ovf_n < OVF_CAP) ? ovf_n : OVF_CAP;
        for (int i = 0; i < ovf_n; i++) {
            uint4 qo = g_ovf[i];
            if ((int)qo.x == gw) {
                unsigned long long p =
                    ((unsigned long long)qo.y << 32) | (unsigned long long)qo.z;
                acc_edge4(acc, p, hl);
            }
        }
    }

    #pragma unroll
    for (int i = 0; i < 8; i++)
        acc[i] += __shfl_xor_sync(0xFFFFFFFFu, acc[i], 16);

    if (half == 0) {
        float4* o4 = reinterpret_cast<float4*>(out) + (size_t)gw * 32 + hl * 2;
        o4[0] = make_float4(acc[0], acc[1], acc[2], acc[3]);
        o4[1] = make_float4(acc[4], acc[5], acc[6], acc[7]);
    }
}

// ---------------------------------------------------------------------------
// Launch sequence: EXACT R12 serial (factor/zero -> scatter -> aggregate)
// ---------------------------------------------------------------------------
extern "C" void kernel_launch(void* const* d_in, const int* in_sizes, int n_in,
                              void* d_out, int out_size) {
    const float* x        = (const float*)d_in[0];
    const int*   adj_rows = (const int*)  d_in[1];
    const int*   adj_cols = (const int*)  d_in[2];
    const float* adj_vals = (const float*)d_in[3];
    float*       out      = (float*)      d_out;

    {
        int blocks = (N_NODES + 31) / 32;
        factor_kernel<<<blocks, 256>>>(x);
    }
    {
        int threads_total = N_EDGES / 4;
        scatter_kernel<<<(threads_total + 255) / 256, 256>>>(adj_rows, adj_cols, adj_vals);
    }
    {
        int blocks = N_NODES / 2;      // 2 nodes per 64-thread block
        aggregate_kernel<<<blocks, 64>>>(out);
    }
}

// round 15
// speedup vs baseline: 1.1130x; 1.0592x over previous
#include <cuda_runtime.h>
#include <cuda_fp16.h>
#include <cstdint>

#define N_NODES 50000
#define D_FEAT  128
#define N_EDGES 800000
#define CAP     64          // per-row bucket capacity (max observed degree ~40)
#define OVF_CAP 4096

// Scratch (device globals; no allocation allowed)
// Bucket entry: (col:16 | val_fp16:16) — N_NODES < 2^16, val quantized to fp16
// with the same cvt.rn used by the R14 aggregate (bit-identical results).
__device__ __half   g_xh[(size_t)N_NODES * D_FEAT];       // 12.8 MB: fp16 tangent
__device__ unsigned g_bucket[(size_t)N_NODES * CAP];      // 12.8 MB (was 25.6)
__device__ int      g_cnt[N_NODES];
__device__ int      g_ovf_cnt;
__device__ uint4    g_ovf[OVF_CAP];                        // {row, col, val_f16_bits, _}

// ---------------------------------------------------------------------------
// Kernel A: logmap0 factor + fp16 tangent convert + zero counters. EXACT R14.
// ---------------------------------------------------------------------------
__global__ __launch_bounds__(256) void factor_kernel(const float* __restrict__ x) {
    const int warp_id = (blockIdx.x * blockDim.x + threadIdx.x) >> 5;
    const int lane    = threadIdx.x & 31;
    const int l       = lane & 7;
    const int row     = warp_id * 4 + (lane >> 3);

    int t = blockIdx.x * blockDim.x + threadIdx.x;
    if (t < N_NODES) g_cnt[t] = 0;
    if (t == 0) g_ovf_cnt = 0;

    if (row >= N_NODES) return;

    const float4* xr = reinterpret_cast<const float4*>(x) + (size_t)row * 32;
    float4 v[4];
    #pragma unroll
    for (int k = 0; k < 4; k++) v[k] = xr[l + 8 * k];

    float ss = 0.f;
    #pragma unroll
    for (int k = 0; k < 4; k++)
        ss += v[k].x * v[k].x + v[k].y * v[k].y + v[k].z * v[k].z + v[k].w * v[k].w;
    ss += __shfl_xor_sync(0xFFFFFFFFu, ss, 1);
    ss += __shfl_xor_sync(0xFFFFFFFFu, ss, 2);
    ss += __shfl_xor_sync(0xFFFFFFFFu, ss, 4);

    // factor = artanh(min(norm, 1-eps)) / max(norm, 1e-15)
    float factor;
    if (ss < 0.0025f) {                      // norm < 0.05: series, err < 1e-12 rel
        factor = 1.0f + ss * (0.33333333f + ss * (0.2f + ss * 0.14285714f));
    } else {                                 // exact fallback (never taken here)
        float norm = fmaxf(sqrtf(ss), 1e-15f);
        float u = fminf(norm, 0.99999988f);
        factor = atanhf(u) / norm;
    }

    uint2* xh = reinterpret_cast<uint2*>(g_xh + (size_t)row * D_FEAT);
    #pragma unroll
    for (int k = 0; k < 4; k++) {
        __half2 lo = __floats2half2_rn(v[k].x * factor, v[k].y * factor);
        __half2 hi = __floats2half2_rn(v[k].z * factor, v[k].w * factor);
        uint2 packed;
        packed.x = *reinterpret_cast<unsigned*>(&lo);
        packed.y = *reinterpret_cast<unsigned*>(&hi);
        xh[l + 8 * k] = packed;
    }
}

// ---------------------------------------------------------------------------
// Kernel B: scatter — CHANGE: pack (col:16 | val_f16:16) into 4B entries.
// Same cvt.rn.f16.f32 the R14 aggregate used, just applied here.
// ---------------------------------------------------------------------------
__global__ __launch_bounds__(256) void scatter_kernel(
    const int* __restrict__ adj_rows,
    const int* __restrict__ adj_cols,
    const float* __restrict__ adj_vals)
{
    int t = blockIdx.x * blockDim.x + threadIdx.x;
    int e0 = t * 4;
    if (e0 >= N_EDGES) return;

    int4   r4 = reinterpret_cast<const int4*>(adj_rows)[t];
    int4   c4 = reinterpret_cast<const int4*>(adj_cols)[t];
    float4 v4 = reinterpret_cast<const float4*>(adj_vals)[t];

    int   r[4] = {r4.x, r4.y, r4.z, r4.w};
    int   c[4] = {c4.x, c4.y, c4.z, c4.w};
    float v[4] = {v4.x, v4.y, v4.z, v4.w};

    #pragma unroll
    for (int k = 0; k < 4; k++) {
        unsigned short vh = __half_as_ushort(__float2half_rn(v[k]));
        unsigned entry = ((unsigned)c[k] << 16) | (unsigned)vh;
        int pos = atomicAdd(&g_cnt[r[k]], 1);
        if (pos < CAP) {
            g_bucket[(size_t)r[k] * CAP + pos] = entry;
        } else {
            int o = atomicAdd(&g_ovf_cnt, 1);
            if (o < OVF_CAP)
                g_ovf[o] = make_uint4((unsigned)r[k], (unsigned)c[k], (unsigned)vh, 0u);
        }
    }
}

// ---------------------------------------------------------------------------
// Kernel C: aggregate — R14 loop (frozen) adapted to 4B bucket entries.
// HFMA mixed-precision accumulate (fp16 x fp16 -> fp32), identical math.
// ---------------------------------------------------------------------------
__device__ __forceinline__ void acc_edge4(float* acc, unsigned p, int hl) {
    const uint4* row = reinterpret_cast<const uint4*>(g_xh + (size_t)(p >> 16) * D_FEAT);
    uint4 q = row[hl];
    unsigned short sh = (unsigned short)(p & 0xFFFFu);

    #pragma unroll
    for (int j = 0; j < 4; j++) {
        unsigned w = (&q.x)[j];
        unsigned short lo = (unsigned short)(w & 0xFFFFu);
        unsigned short hi = (unsigned short)(w >> 16);
        asm("fma.rn.f32.f16 %0, %1, %2, %0;" : "+f"(acc[2*j])     : "h"(lo), "h"(sh));
        asm("fma.rn.f32.f16 %0, %1, %2, %0;" : "+f"(acc[2*j + 1]) : "h"(hi), "h"(sh));
    }
}

__global__ __launch_bounds__(64) void aggregate_kernel(float* __restrict__ out) {
    int gw   = (blockIdx.x * blockDim.x + threadIdx.x) >> 5;
    int lane = threadIdx.x & 31;
    if (gw >= N_NODES) return;

    const int half = lane >> 4;
    const int hl   = lane & 15;

    int raw_n = g_cnt[gw];
    int n = (raw_n < CAP) ? raw_n : CAP;
    const unsigned* bk = g_bucket + (size_t)gw * CAP;

    float acc[8] = {0.f, 0.f, 0.f, 0.f, 0.f, 0.f, 0.f, 0.f};

    int e = 0;
    for (; e + 4 <= n; e += 4) {
        unsigned p0 = bk[e + half];
        unsigned p1 = bk[e + 2 + half];
        acc_edge4(acc, p0, hl);
        acc_edge4(acc, p1, hl);
    }
    if (e + 2 <= n) {
        acc_edge4(acc, bk[e + half], hl);
        e += 2;
    }
    if (e < n && half == 0) {
        acc_edge4(acc, bk[e], hl);
    }

    if (raw_n > CAP && half == 0) {
        int ovf_n = g_ovf_cnt;
        ovf_n = (ovf_n < OVF_CAP) ? ovf_n : OVF_CAP;
        for (int i = 0; i < ovf_n; i++) {
            uint4 qo = g_ovf[i];
            if ((int)qo.x == gw) {
                unsigned p = (qo.y << 16) | (qo.z & 0xFFFFu);
                acc_edge4(acc, p, hl);
            }
        }
    }

    #pragma unroll
    for (int i = 0; i < 8; i++)
        acc[i] += __shfl_xor_sync(0xFFFFFFFFu, acc[i], 16);

    if (half == 0) {
        float4* o4 = reinterpret_cast<float4*>(out) + (size_t)gw * 32 + hl * 2;
        o4[0] = make_float4(acc[0], acc[1], acc[2], acc[3]);
        o4[1] = make_float4(acc[4], acc[5], acc[6], acc[7]);
    }
}

// ---------------------------------------------------------------------------
// Launch sequence: EXACT R12/R14 serial (factor/zero -> scatter -> aggregate)
// ---------------------------------------------------------------------------
extern "C" void kernel_launch(void* const* d_in, const int* in_sizes, int n_in,
                              void* d_out, int out_size) {
    const float* x        = (const float*)d_in[0];
    const int*   adj_rows = (const int*)  d_in[1];
    const int*   adj_cols = (const int*)  d_in[2];
    const float* adj_vals = (const float*)d_in[3];
    float*       out      = (float*)      d_out;

    {
        int blocks = (N_NODES + 31) / 32;
        factor_kernel<<<blocks, 256>>>(x);
    }
    {
        int threads_total = N_EDGES / 4;
        scatter_kernel<<<(threads_total + 255) / 256, 256>>>(adj_rows, adj_cols, adj_vals);
    }
    {
        int blocks = N_NODES / 2;      // 2 nodes per 64-thread block
        aggregate_kernel<<<blocks, 64>>>(out);
    }
}